// round 15
// baseline (speedup 1.0000x reference)
#include <cuda_runtime.h>
#include <cuda_fp16.h>
#include <cstdint>

#define Bb 2
#define Ss 2048
#define Dd 1024
#define Hh 16
#define BSD (Bb * Ss * Dd) /* 4194304 */
#define DD (Dd * Dd)

// fp32 scratch (cache fallback)
static __device__ float g_k[BSD];
static __device__ float g_v[BSD];
// half scratch
static __device__ __half g_xq[BSD], g_xk[BSD], g_xv[BSD];
static __device__ __half g_qh[BSD], g_kh[BSD], g_vh[BSD];
static __device__ __half g_ah[BSD];
static __device__ __half g_wqh[DD], g_wkh[DD], g_wvh[DD], g_woh[DD];

__device__ __forceinline__ unsigned f2h2(float lo, float hi) {
    __half2 h = __floats2half2_rn(lo, hi);
    return *(unsigned*)&h;
}

__device__ __forceinline__ void mma16(float* c, const unsigned* a, const unsigned* b) {
    asm volatile(
        "mma.sync.aligned.m16n8k16.row.col.f32.f16.f16.f32 "
        "{%0,%1,%2,%3}, {%4,%5,%6,%7}, {%8,%9}, {%0,%1,%2,%3};\n"
        : "+f"(c[0]), "+f"(c[1]), "+f"(c[2]), "+f"(c[3])
        : "r"(a[0]), "r"(a[1]), "r"(a[2]), "r"(a[3]), "r"(b[0]), "r"(b[1]));
}

__device__ __forceinline__ uint32_t smem_u32(const void* p) {
    uint32_t a;
    asm("{ .reg .u64 t; cvta.to.shared.u64 t, %1; cvt.u32.u64 %0, t; }"
        : "=r"(a) : "l"(p));
    return a;
}

#define CP_ASYNC16(dst, src) \
    asm volatile("cp.async.cg.shared.global [%0], [%1], 16;" :: "r"(dst), "l"(src))
#define CP_COMMIT() asm volatile("cp.async.commit_group;" ::: "memory")
#define CP_WAIT(n)  asm volatile("cp.async.wait_group %0;" :: "n"(n) : "memory")

#define LDSM_X4(r0, r1, r2, r3, addr)                                          \
    asm volatile("ldmatrix.sync.aligned.m8n8.x4.shared.b16 "                   \
                 "{%0,%1,%2,%3}, [%4];"                                        \
                 : "=r"(r0), "=r"(r1), "=r"(r2), "=r"(r3) : "r"(addr))

#define LDSM_X4_T(r0, r1, r2, r3, addr)                                        \
    asm volatile("ldmatrix.sync.aligned.m8n8.x4.trans.shared.b16 "             \
                 "{%0,%1,%2,%3}, [%4];"                                        \
                 : "=r"(r0), "=r"(r1), "=r"(r2), "=r"(r3) : "r"(addr))

// ===========================================================================
// Pre-convert fp32 -> fp16 (3 inputs + 4 weights), 8 elts/thread
// ===========================================================================
__global__ __launch_bounds__(256, 4)
void cvt7(const float* q, const float* k, const float* v,
          const float* wq, const float* wk, const float* wv, const float* wo,
          __half* qh, __half* kh, __half* vh,
          __half* wqh, __half* wkh, __half* wvh, __half* woh)
{
    const int z = blockIdx.y;
    const float* s; __half* d; int n;
    switch (z) {
        case 0: s = q;  d = qh;  n = BSD; break;
        case 1: s = k;  d = kh;  n = BSD; break;
        case 2: s = v;  d = vh;  n = BSD; break;
        case 3: s = wq; d = wqh; n = DD;  break;
        case 4: s = wk; d = wkh; n = DD;  break;
        case 5: s = wv; d = wvh; n = DD;  break;
        default: s = wo; d = woh; n = DD; break;
    }
    const size_t i = ((size_t)blockIdx.x * 256 + threadIdx.x) * 8;
    if (i >= (size_t)n) return;
    const float4 a = *(const float4*)(s + i);
    const float4 b2 = *(const float4*)(s + i + 4);
    uint4 u = {f2h2(a.x, a.y), f2h2(a.z, a.w), f2h2(b2.x, b2.y), f2h2(b2.z, b2.w)};
    *(uint4*)(d + i) = u;
}

// ===========================================================================
// GEMM (half): C = A @ W^T + bias, N=K=1024 compile-time. 128x128 CTA tile,
// BK=64, 128 thr / 4 warps, warp tile 64x64 (4 mma per ldsm), 3-stage
// cp.async pipeline, ONE syncthreads per chunk. 2 CTAs/SM, ~185 regs/thr.
// ===========================================================================
#define GK 1024
#define GN 1024
#define GST64 36                         /* u32 stride: 32 data + 4 pad      */
#define GBUF64 (128 * GST64)             /* 4608 u32 per operand stage       */
#define GSM_BYTES (6 * GBUF64 * 4)       /* 110592 B (2 CTAs = 216 KB)       */
#define GNCH 16                          /* 1024 / 64                        */

__device__ __forceinline__
void gemm_core(const __half* __restrict__ A, const __half* __restrict__ W,
               const float* __restrict__ bias, float* Cf, __half* Ch,
               int bm, int bn, unsigned* smbase)
{
    const int tid = threadIdx.x;
    const int w = tid >> 5, lane = tid & 31;
    const int g = lane >> 2, t = lane & 3;
    const int wm = (w & 1) * 64;
    const int wn = (w >> 1) * 64;
    const int row16 = lane & 15;
    const int koff = (lane >> 4) * 4;

    const uint32_t sA = smem_u32(smbase);
    const uint32_t sB = sA + (uint32_t)(3 * GBUF64) * 4;

    // staging: 128 rows x 8 segs (16B) per operand; 8 rows/thread/operand
    const int srow = tid >> 3;   // 0..15 (+16*l)
    const int sseg = tid & 7;    // 0..7

    float c[4][8][4] = {};

#define G_ISSUE(st, ch) do {                                                   \
        const int _k0 = (ch) * 64 + sseg * 8;                                  \
        _Pragma("unroll")                                                      \
        for (int _l = 0; _l < 8; _l++) {                                       \
            const int _row = srow + 16 * _l;                                   \
            const uint32_t _off =                                              \
                (uint32_t)((st) * GBUF64 + _row * GST64 + sseg * 4) * 4;       \
            CP_ASYNC16(sA + _off, A + (size_t)(bm + _row) * GK + _k0);         \
            CP_ASYNC16(sB + _off, W + (size_t)(bn + _row) * GK + _k0);         \
        }                                                                      \
    } while (0)

    G_ISSUE(0, 0); CP_COMMIT();
    G_ISSUE(1, 1); CP_COMMIT();

    for (int ch = 0; ch < GNCH; ch++) {
        CP_WAIT(1);
        __syncthreads();
        if (ch + 2 < GNCH) G_ISSUE((ch + 2) % 3, ch + 2);
        CP_COMMIT();

        const uint32_t sAc = sA + (uint32_t)((ch % 3) * GBUF64) * 4;
        const uint32_t sBc = sB + (uint32_t)((ch % 3) * GBUF64) * 4;
#pragma unroll
        for (int kk = 0; kk < 4; kk++) {
            const int kb = kk * 8;
            unsigned a[4][4];
#pragma unroll
            for (int mt = 0; mt < 4; mt++) {
                const uint32_t addr = sAc +
                    (uint32_t)((wm + mt * 16 + row16) * GST64 + kb + koff) * 4;
                LDSM_X4(a[mt][0], a[mt][1], a[mt][2], a[mt][3], addr);
            }
#pragma unroll
            for (int ntp = 0; ntp < 4; ntp++) {
                unsigned bv[4];
                const uint32_t addr = sBc +
                    (uint32_t)((wn + ntp * 16 + row16) * GST64 + kb + koff) * 4;
                LDSM_X4(bv[0], bv[1], bv[2], bv[3], addr);
                unsigned be[2] = {bv[0], bv[2]};
                unsigned bo2[2] = {bv[1], bv[3]};
#pragma unroll
                for (int mt = 0; mt < 4; mt++) {
                    mma16(c[mt][2 * ntp],     a[mt], be);
                    mma16(c[mt][2 * ntp + 1], a[mt], bo2);
                }
            }
        }
    }
#undef G_ISSUE

#pragma unroll
    for (int mt = 0; mt < 4; mt++) {
        const int r0 = bm + wm + mt * 16 + g;
#pragma unroll
        for (int nt = 0; nt < 8; nt++) {
            const int col = bn + wn + nt * 8 + 2 * t;
            const float2 bv = *(const float2*)(bias + col);
            float2 o0 = {c[mt][nt][0] + bv.x, c[mt][nt][1] + bv.y};
            float2 o1 = {c[mt][nt][2] + bv.x, c[mt][nt][3] + bv.y};
            if (Cf) {
                *(float2*)(Cf + (size_t)r0 * GN + col) = o0;
                *(float2*)(Cf + (size_t)(r0 + 8) * GN + col) = o1;
            }
            if (Ch) {
                *(unsigned*)(Ch + (size_t)r0 * GN + col) = f2h2(o0.x, o0.y);
                *(unsigned*)(Ch + (size_t)(r0 + 8) * GN + col) = f2h2(o1.x, o1.y);
            }
        }
    }
}

__global__ __launch_bounds__(128, 2)
void gemm_h(const __half* __restrict__ A, const __half* __restrict__ W,
            const float* __restrict__ bias, float* Cf, __half* Ch)
{
    extern __shared__ unsigned dsm[];
    gemm_core(A, W, bias, Cf, Ch, blockIdx.y * 128, blockIdx.x * 128, dsm);
}

__global__ __launch_bounds__(128, 2)
void qkv_gemm(const __half* xq, const __half* xk, const __half* xv,
              const __half* wq, const __half* wk, const __half* wv,
              const float* b0, const float* b1, const float* b2,
              __half* qh, float* kf, __half* kh, float* vf, __half* vh)
{
    extern __shared__ unsigned dsm[];
    const int z = blockIdx.z;
    const __half* A = (z == 0) ? xq : (z == 1) ? xk : xv;
    const __half* W = (z == 0) ? wq : (z == 1) ? wk : wv;
    const float* bi = (z == 0) ? b0 : (z == 1) ? b1 : b2;
    float* Cf = (z == 0) ? nullptr : (z == 1) ? kf : vf;
    __half* Ch = (z == 0) ? qh : (z == 1) ? kh : vh;
    gemm_core(A, W, bi, Cf, Ch, blockIdx.y * 128, blockIdx.x * 128, dsm);
}

// ===========================================================================
// Attention: 256 thr / 8 warps (16 q-rows each), 2 CTAs/SM, k-tiles of 64
// (32 iterations). 3-stage cp.async K/V pipeline, ONE syncthreads/iter.
// Q fragments hoisted; bias prefetched as packed half2 (pre-scaled by log2e).
// ldmatrix for K/P, ldmatrix.trans for V. (verbatim from R13/R14)
// ===========================================================================
#define KTILE 64
#define QSTH 36
#define KSTH 36
#define VSTH 36
#define PSTH 36
#define KBUFU (KTILE * KSTH)   /* 2304 */
#define VBUFU (KTILE * VSTH)   /* 2304 */
#define AO_K 4608                       /* after Qs 128*36 */
#define AO_V (AO_K + 3 * KBUFU)         /* 11520 */
#define AO_P (AO_V + 3 * VBUFU)         /* 18432 */
#define ATTN_UINTS (AO_P + 128 * PSTH)  /* 23040 */
#define ATTN_SM_BYTES (ATTN_UINTS * 4)  /* 92160 */
#define QPRE 0.18033688011112042f       /* 0.125 * log2(e) */
#define LOG2E 1.4426950408889634f

__global__ __launch_bounds__(256, 2)
void attn_h(const __half* __restrict__ Q, const __half* __restrict__ Kh,
            const __half* __restrict__ Vh, const float* __restrict__ bias,
            __half* __restrict__ O)
{
    extern __shared__ unsigned dsm[];
    unsigned* Ps = dsm + AO_P;

    const int tid = threadIdx.x;
    const int w = tid >> 5, lane = tid & 31;
    const int g = lane >> 2, t = lane & 3;
    const int row16 = lane & 15;
    const int koff = (lane >> 4) * 4;
    const int q0 = blockIdx.x * 128;
    const int bh = blockIdx.y;
    const int b = bh >> 4, h = bh & 15;

    const uint32_t sQ = smem_u32(dsm);
    const uint32_t sK = smem_u32(dsm + AO_K);
    const uint32_t sV = smem_u32(dsm + AO_V);
    const uint32_t sPw = smem_u32(Ps) + (uint32_t)(w * 16 * PSTH) * 4;
    unsigned* Pw = Ps + w * 16 * PSTH;

    const int srow = tid >> 3;        // 0..31
    const int sseg = tid & 7;         // 0..7
    const __half* KbBase = Kh + (size_t)b * Ss * Dd + h * 64 + sseg * 8;
    const __half* VbBase = Vh + (size_t)b * Ss * Dd + h * 64 + sseg * 8;
    const float* biasBase = bias + (size_t)b * Ss * Ss + (size_t)(q0 + w * 16 + g) * Ss;

#define A_ISSUE(st, it_) do {                                                  \
        _Pragma("unroll")                                                      \
        for (int _l = 0; _l < 2; _l++) {                                       \
            const int _row = srow + 32 * _l;                                   \
            const size_t _roff = (size_t)((it_) * KTILE + _row) * Dd;          \
            const uint32_t _off = (uint32_t)(_row * KSTH + sseg * 4) * 4;      \
            CP_ASYNC16(sK + (uint32_t)((st) * KBUFU) * 4 + _off, KbBase + _roff); \
            CP_ASYNC16(sV + (uint32_t)((st) * VBUFU) * 4 + _off, VbBase + _roff); \
        }                                                                      \
    } while (0)

    {
        A_ISSUE(0, 0);
        const __half* Qb = Q + ((size_t)b * Ss + q0) * Dd + h * 64 + sseg * 8;
#pragma unroll
        for (int l = 0; l < 4; l++) {
            const int row = srow + 32 * l;
            CP_ASYNC16(sQ + (uint32_t)(row * QSTH + sseg * 4) * 4,
                       Qb + (size_t)row * Dd);
        }
    }
    CP_COMMIT();
    A_ISSUE(1, 1);
    CP_COMMIT();

    unsigned pbh[8][2];
#pragma unroll
    for (int nt = 0; nt < 8; nt++)
#pragma unroll
        for (int rr = 0; rr < 2; rr++) {
            float2 v = *(const float2*)(biasBase + (size_t)(rr * 8) * Ss + nt * 8 + 2 * t);
            pbh[nt][rr] = f2h2(v.x * LOG2E, v.y * LOG2E);
        }

    CP_WAIT(1);
    __syncthreads();

    unsigned qa[4][4];
#pragma unroll
    for (int kk = 0; kk < 4; kk++) {
        const uint32_t addr = sQ +
            (uint32_t)((w * 16 + row16) * QSTH + kk * 8 + koff) * 4;
        LDSM_X4(qa[kk][0], qa[kk][1], qa[kk][2], qa[kk][3], addr);
    }

    float o[8][4] = {};
    float lr[2] = {};

    const int NIT = Ss / KTILE;   // 32
    for (int it = 0; it < NIT; it++) {
        if (it > 0) {
            CP_WAIT(1);
            __syncthreads();
        }
        if (it + 2 < NIT) A_ISSUE((it + 2) % 3, it + 2);
        CP_COMMIT();

        const uint32_t sKc = sK + (uint32_t)((it % 3) * KBUFU) * 4;
        const uint32_t vb = sV + (uint32_t)((it % 3) * VBUFU) * 4;

        float s[8][4] = {};
#pragma unroll
        for (int kk = 0; kk < 4; kk++) {
            const int kb = kk * 8;
#pragma unroll
            for (int ntp = 0; ntp < 4; ntp++) {
                unsigned kv[4];
                const uint32_t addr = sKc +
                    (uint32_t)((ntp * 16 + row16) * KSTH + kb + koff) * 4;
                LDSM_X4(kv[0], kv[1], kv[2], kv[3], addr);
                unsigned be[2] = {kv[0], kv[2]};
                unsigned bo2[2] = {kv[1], kv[3]};
                mma16(s[2 * ntp],     qa[kk], be);
                mma16(s[2 * ntp + 1], qa[kk], bo2);
            }
        }

#pragma unroll
        for (int nt = 0; nt < 8; nt++) {
            const float2 b0 = __half22float2(*(__half2*)&pbh[nt][0]);
            const float2 b1 = __half22float2(*(__half2*)&pbh[nt][1]);
            float p0 = exp2f(fmaf(s[nt][0], QPRE, b0.x));
            float p1 = exp2f(fmaf(s[nt][1], QPRE, b0.y));
            float p2 = exp2f(fmaf(s[nt][2], QPRE, b1.x));
            float p3 = exp2f(fmaf(s[nt][3], QPRE, b1.y));
            lr[0] += p0 + p1;
            lr[1] += p2 + p3;
            Pw[(g) * PSTH + nt * 4 + t]     = f2h2(p0, p1);
            Pw[(g + 8) * PSTH + nt * 4 + t] = f2h2(p2, p3);
        }

        if (it + 1 < NIT) {
            const float* bp = biasBase + (it + 1) * KTILE;
#pragma unroll
            for (int nt = 0; nt < 8; nt++)
#pragma unroll
                for (int rr = 0; rr < 2; rr++) {
                    float2 v = *(const float2*)(bp + (size_t)(rr * 8) * Ss + nt * 8 + 2 * t);
                    pbh[nt][rr] = f2h2(v.x * LOG2E, v.y * LOG2E);
                }
        }
        __syncwarp();

        const int m = lane >> 3, rr2 = lane & 7;
#pragma unroll
        for (int kk = 0; kk < 4; kk++) {
            const int kb = kk * 8;
            unsigned pa[4];
            const uint32_t paddr = sPw + (uint32_t)(row16 * PSTH + kb + koff) * 4;
            LDSM_X4(pa[0], pa[1], pa[2], pa[3], paddr);
#pragma unroll
            for (int ntp = 0; ntp < 4; ntp++) {
                const uint32_t vaddr = vb +
                    (uint32_t)((kk * 16 + (m & 1) * 8 + rr2) * VSTH +
                               (2 * ntp + (m >> 1)) * 4) * 4;
                unsigned bv[4];
                LDSM_X4_T(bv[0], bv[1], bv[2], bv[3], vaddr);
                mma16(o[2 * ntp],     pa, &bv[0]);
                mma16(o[2 * ntp + 1], pa, &bv[2]);
            }
        }
    }
#undef A_ISSUE

#pragma unroll
    for (int hf = 0; hf < 2; hf++) {
        float v = lr[hf];
        v += __shfl_xor_sync(0xffffffffu, v, 1);
        v += __shfl_xor_sync(0xffffffffu, v, 2);
        lr[hf] = 1.f / v;
    }

    __half* Ob = O + ((size_t)b * Ss + q0 + w * 16) * Dd + h * 64;
#pragma unroll
    for (int nt = 0; nt < 8; nt++) {
        const int cg = nt * 8 + 2 * t;
        *(unsigned*)(Ob + (size_t)g * Dd + cg) =
            f2h2(o[nt][0] * lr[0], o[nt][1] * lr[0]);
        *(unsigned*)(Ob + (size_t)(g + 8) * Dd + cg) =
            f2h2(o[nt][2] * lr[1], o[nt][3] * lr[1]);
    }
}

// ---------------------------------------------------------------------------
extern "C" void kernel_launch(void* const* d_in, const int* in_sizes, int n_in,
                              void* d_out, int out_size)
{
    (void)in_sizes; (void)n_in;
    const float* queries   = (const float*)d_in[0];
    const float* keys      = (const float*)d_in[1];
    const float* values    = (const float*)d_in[2];
    const float* attn_bias = (const float*)d_in[3];
    const float* Wq = (const float*)d_in[4];
    const float* bq = (const float*)d_in[5];
    const float* Wk = (const float*)d_in[6];
    const float* bk = (const float*)d_in[7];
    const float* Wv = (const float*)d_in[8];
    const float* bv = (const float*)d_in[9];
    const float* Wo = (const float*)d_in[10];
    const float* bo = (const float*)d_in[11];

    float* out = (float*)d_out;

    float *pkf, *pvf;
    cudaGetSymbolAddress((void**)&pkf, g_k);
    cudaGetSymbolAddress((void**)&pvf, g_v);
    __half *xq, *xk, *xv, *qh, *kh, *vh, *ah, *wqh, *wkh, *wvh, *woh;
    cudaGetSymbolAddress((void**)&xq,  g_xq);
    cudaGetSymbolAddress((void**)&xk,  g_xk);
    cudaGetSymbolAddress((void**)&xv,  g_xv);
    cudaGetSymbolAddress((void**)&qh,  g_qh);
    cudaGetSymbolAddress((void**)&kh,  g_kh);
    cudaGetSymbolAddress((void**)&vh,  g_vh);
    cudaGetSymbolAddress((void**)&ah,  g_ah);
    cudaGetSymbolAddress((void**)&wqh, g_wqh);
    cudaGetSymbolAddress((void**)&wkh, g_wkh);
    cudaGetSymbolAddress((void**)&wvh, g_wvh);
    cudaGetSymbolAddress((void**)&woh, g_woh);

    const bool full_out = (out_size >= 3 * BSD);
    float* kdst = full_out ? out + BSD     : pkf;
    float* vdst = full_out ? out + 2 * BSD : pvf;

    cudaFuncSetAttribute(gemm_h, cudaFuncAttributeMaxDynamicSharedMemorySize,
                         GSM_BYTES);
    cudaFuncSetAttribute(qkv_gemm, cudaFuncAttributeMaxDynamicSharedMemorySize,
                         GSM_BYTES);
    cudaFuncSetAttribute(attn_h, cudaFuncAttributeMaxDynamicSharedMemorySize,
                         ATTN_SM_BYTES);

    dim3 cgrid(BSD / (256 * 8), 7);
    cvt7<<<cgrid, 256>>>(queries, keys, values, Wq, Wk, Wv, Wo,
                         xq, xk, xv, wqh, wkh, wvh, woh);

    dim3 qkvgrid(Dd / 128, (Bb * Ss) / 128, 3);  // (8, 32, 3)
    qkv_gemm<<<qkvgrid, 128, GSM_BYTES>>>(xq, xk, xv, wqh, wkh, wvh, bq, bk, bv,
                                          qh, kdst, kh, vdst, vh);

    dim3 agrid(Ss / 128, Bb * Hh);               // (16, 32)
    attn_h<<<agrid, 256, ATTN_SM_BYTES>>>(qh, kh, vh, attn_bias, ah);

    dim3 ggrid(Dd / 128, (Bb * Ss) / 128);       // (8, 32)
    gemm_h<<<ggrid, 128, GSM_BYTES>>>(ah, woh, bo, out, nullptr);
}

// round 16
// speedup vs baseline: 1.0034x; 1.0034x over previous
#include <cuda_runtime.h>
#include <cuda_fp16.h>
#include <cstdint>

#define Bb 2
#define Ss 2048
#define Dd 1024
#define Hh 16
#define BSD (Bb * Ss * Dd) /* 4194304 */
#define BSS (Bb * Ss * Ss) /* 8388608 */
#define DD (Dd * Dd)

// fp32 scratch (cache fallback)
static __device__ float g_k[BSD];
static __device__ float g_v[BSD];
// half scratch
static __device__ __half g_xq[BSD], g_xk[BSD], g_xv[BSD];
static __device__ __half g_qh[BSD], g_kh[BSD], g_vh[BSD];
static __device__ __half g_ah[BSD];
static __device__ __half g_wqh[DD], g_wkh[DD], g_wvh[DD], g_woh[DD];
static __device__ __half g_bh[BSS];   // bias * log2e, half

#define LOG2E 1.4426950408889634f
#define QPRE 0.18033688011112042f     /* 0.125 * log2(e) */

__device__ __forceinline__ unsigned f2h2(float lo, float hi) {
    __half2 h = __floats2half2_rn(lo, hi);
    return *(unsigned*)&h;
}

__device__ __forceinline__ void mma16(float* c, const unsigned* a, const unsigned* b) {
    asm volatile(
        "mma.sync.aligned.m16n8k16.row.col.f32.f16.f16.f32 "
        "{%0,%1,%2,%3}, {%4,%5,%6,%7}, {%8,%9}, {%0,%1,%2,%3};\n"
        : "+f"(c[0]), "+f"(c[1]), "+f"(c[2]), "+f"(c[3])
        : "r"(a[0]), "r"(a[1]), "r"(a[2]), "r"(a[3]), "r"(b[0]), "r"(b[1]));
}

__device__ __forceinline__ uint32_t smem_u32(const void* p) {
    uint32_t a;
    asm("{ .reg .u64 t; cvta.to.shared.u64 t, %1; cvt.u32.u64 %0, t; }"
        : "=r"(a) : "l"(p));
    return a;
}

#define CP_ASYNC16(dst, src) \
    asm volatile("cp.async.cg.shared.global [%0], [%1], 16;" :: "r"(dst), "l"(src))
#define CP_COMMIT() asm volatile("cp.async.commit_group;" ::: "memory")
#define CP_WAIT(n)  asm volatile("cp.async.wait_group %0;" :: "n"(n) : "memory")

#define LDSM_X4(r0, r1, r2, r3, addr)                                          \
    asm volatile("ldmatrix.sync.aligned.m8n8.x4.shared.b16 "                   \
                 "{%0,%1,%2,%3}, [%4];"                                        \
                 : "=r"(r0), "=r"(r1), "=r"(r2), "=r"(r3) : "r"(addr))

#define LDSM_X4_T(r0, r1, r2, r3, addr)                                        \
    asm volatile("ldmatrix.sync.aligned.m8n8.x4.trans.shared.b16 "             \
                 "{%0,%1,%2,%3}, [%4];"                                        \
                 : "=r"(r0), "=r"(r1), "=r"(r2), "=r"(r3) : "r"(addr))

// ===========================================================================
// Pre-convert fp32 -> fp16: 3 inputs, 4 weights, and bias*log2e. 8 elts/thr.
// ===========================================================================
__global__ __launch_bounds__(256, 4)
void cvt8(const float* q, const float* k, const float* v,
          const float* wq, const float* wk, const float* wv, const float* wo,
          const float* bias,
          __half* qh, __half* kh, __half* vh,
          __half* wqh, __half* wkh, __half* wvh, __half* woh, __half* bh)
{
    const int z = blockIdx.y;
    const float* s; __half* d; int n; float sc = 1.0f;
    switch (z) {
        case 0: s = q;  d = qh;  n = BSD; break;
        case 1: s = k;  d = kh;  n = BSD; break;
        case 2: s = v;  d = vh;  n = BSD; break;
        case 3: s = wq; d = wqh; n = DD;  break;
        case 4: s = wk; d = wkh; n = DD;  break;
        case 5: s = wv; d = wvh; n = DD;  break;
        case 6: s = wo; d = woh; n = DD;  break;
        default: s = bias; d = bh; n = BSS; sc = LOG2E; break;
    }
    const size_t i = ((size_t)blockIdx.x * 256 + threadIdx.x) * 8;
    if (i >= (size_t)n) return;
    const float4 a = *(const float4*)(s + i);
    const float4 b2 = *(const float4*)(s + i + 4);
    uint4 u = {f2h2(a.x * sc, a.y * sc), f2h2(a.z * sc, a.w * sc),
               f2h2(b2.x * sc, b2.y * sc), f2h2(b2.z * sc, b2.w * sc)};
    *(uint4*)(d + i) = u;
}

// ===========================================================================
// GEMM (half): C = A @ W^T + bias, N=K=1024 compile-time. 128x128 CTA tile,
// BK=64, 256 thr / 8 warps, warp tile 32x64, 3-stage cp.async pipeline,
// ONE syncthreads per chunk. 2 CTAs/SM. (R14 config — measured best.)
// ===========================================================================
#define GK 1024
#define GN 1024
#define GST64 36
#define GBUF64 (128 * GST64)
#define GSM_BYTES (6 * GBUF64 * 4)       /* 110592 */
#define GNCH 16

__device__ __forceinline__
void gemm_core(const __half* __restrict__ A, const __half* __restrict__ W,
               const float* __restrict__ bias, float* Cf, __half* Ch,
               int bm, int bn, unsigned* smbase)
{
    const int tid = threadIdx.x;
    const int w = tid >> 5, lane = tid & 31;
    const int g = lane >> 2, t = lane & 3;
    const int wm = (w & 3) * 32;
    const int wn = (w >> 2) * 64;
    const int row16 = lane & 15;
    const int koff = (lane >> 4) * 4;

    const uint32_t sA = smem_u32(smbase);
    const uint32_t sB = sA + (uint32_t)(3 * GBUF64) * 4;

    const int srow = tid >> 3;   // 0..31 (+32*l)
    const int sseg = tid & 7;    // 0..7

    float c[2][8][4] = {};

#define G_ISSUE(st, ch) do {                                                   \
        const int _k0 = (ch) * 64 + sseg * 8;                                  \
        _Pragma("unroll")                                                      \
        for (int _l = 0; _l < 4; _l++) {                                       \
            const int _row = srow + 32 * _l;                                   \
            const uint32_t _off =                                              \
                (uint32_t)((st) * GBUF64 + _row * GST64 + sseg * 4) * 4;       \
            CP_ASYNC16(sA + _off, A + (size_t)(bm + _row) * GK + _k0);         \
            CP_ASYNC16(sB + _off, W + (size_t)(bn + _row) * GK + _k0);         \
        }                                                                      \
    } while (0)

    G_ISSUE(0, 0); CP_COMMIT();
    G_ISSUE(1, 1); CP_COMMIT();

    for (int ch = 0; ch < GNCH; ch++) {
        CP_WAIT(1);
        __syncthreads();
        if (ch + 2 < GNCH) G_ISSUE((ch + 2) % 3, ch + 2);
        CP_COMMIT();

        const uint32_t sAc = sA + (uint32_t)((ch % 3) * GBUF64) * 4;
        const uint32_t sBc = sB + (uint32_t)((ch % 3) * GBUF64) * 4;
#pragma unroll
        for (int kk = 0; kk < 4; kk++) {
            const int kb = kk * 8;
            unsigned a[2][4];
#pragma unroll
            for (int mt = 0; mt < 2; mt++) {
                const uint32_t addr = sAc +
                    (uint32_t)((wm + mt * 16 + row16) * GST64 + kb + koff) * 4;
                LDSM_X4(a[mt][0], a[mt][1], a[mt][2], a[mt][3], addr);
            }
#pragma unroll
            for (int ntp = 0; ntp < 4; ntp++) {
                unsigned bv[4];
                const uint32_t addr = sBc +
                    (uint32_t)((wn + ntp * 16 + row16) * GST64 + kb + koff) * 4;
                LDSM_X4(bv[0], bv[1], bv[2], bv[3], addr);
                unsigned be[2] = {bv[0], bv[2]};
                unsigned bo2[2] = {bv[1], bv[3]};
                mma16(c[0][2 * ntp],     a[0], be);
                mma16(c[1][2 * ntp],     a[1], be);
                mma16(c[0][2 * ntp + 1], a[0], bo2);
                mma16(c[1][2 * ntp + 1], a[1], bo2);
            }
        }
    }
#undef G_ISSUE

#pragma unroll
    for (int mt = 0; mt < 2; mt++) {
        const int r0 = bm + wm + mt * 16 + g;
#pragma unroll
        for (int nt = 0; nt < 8; nt++) {
            const int col = bn + wn + nt * 8 + 2 * t;
            const float2 bv = *(const float2*)(bias + col);
            float2 o0 = {c[mt][nt][0] + bv.x, c[mt][nt][1] + bv.y};
            float2 o1 = {c[mt][nt][2] + bv.x, c[mt][nt][3] + bv.y};
            if (Cf) {
                *(float2*)(Cf + (size_t)r0 * GN + col) = o0;
                *(float2*)(Cf + (size_t)(r0 + 8) * GN + col) = o1;
            }
            if (Ch) {
                *(unsigned*)(Ch + (size_t)r0 * GN + col) = f2h2(o0.x, o0.y);
                *(unsigned*)(Ch + (size_t)(r0 + 8) * GN + col) = f2h2(o1.x, o1.y);
            }
        }
    }
}

__global__ __launch_bounds__(256, 2)
void gemm_h(const __half* __restrict__ A, const __half* __restrict__ W,
            const float* __restrict__ bias, float* Cf, __half* Ch)
{
    extern __shared__ unsigned dsm[];
    gemm_core(A, W, bias, Cf, Ch, blockIdx.y * 128, blockIdx.x * 128, dsm);
}

__global__ __launch_bounds__(256, 2)
void qkv_gemm(const __half* xq, const __half* xk, const __half* xv,
              const __half* wq, const __half* wk, const __half* wv,
              const float* b0, const float* b1, const float* b2,
              __half* qh, float* kf, __half* kh, float* vf, __half* vh)
{
    extern __shared__ unsigned dsm[];
    const int z = blockIdx.z;
    const __half* A = (z == 0) ? xq : (z == 1) ? xk : xv;
    const __half* W = (z == 0) ? wq : (z == 1) ? wk : wv;
    const float* bi = (z == 0) ? b0 : (z == 1) ? b1 : b2;
    float* Cf = (z == 0) ? nullptr : (z == 1) ? kf : vf;
    __half* Ch = (z == 0) ? qh : (z == 1) ? kh : vh;
    gemm_core(A, W, bi, Cf, Ch, blockIdx.y * 128, blockIdx.x * 128, dsm);
}

// ===========================================================================
// Attention: 256 thr / 8 warps (16 q-rows each), 2 CTAs/SM, k-tiles of 64
// (32 iterations). 3-stage cp.async K/V pipeline, ONE syncthreads/iter.
// Q fragments hoisted. Bias loaded directly as pre-scaled half2 (g_bh):
// zero in-loop conversion, half the bias memory traffic vs fp32.
// ldmatrix for K/P, ldmatrix.trans for V.
// ===========================================================================
#define KTILE 64
#define QSTH 36
#define KSTH 36
#define VSTH 36
#define PSTH 36
#define KBUFU (KTILE * KSTH)   /* 2304 */
#define VBUFU (KTILE * VSTH)   /* 2304 */
#define AO_K 4608
#define AO_V (AO_K + 3 * KBUFU)
#define AO_P (AO_V + 3 * VBUFU)
#define ATTN_UINTS (AO_P + 128 * PSTH)
#define ATTN_SM_BYTES (ATTN_UINTS * 4)  /* 92160 */

__global__ __launch_bounds__(256, 2)
void attn_h(const __half* __restrict__ Q, const __half* __restrict__ Kh,
            const __half* __restrict__ Vh, const __half* __restrict__ biasH,
            __half* __restrict__ O)
{
    extern __shared__ unsigned dsm[];
    unsigned* Ps = dsm + AO_P;

    const int tid = threadIdx.x;
    const int w = tid >> 5, lane = tid & 31;
    const int g = lane >> 2, t = lane & 3;
    const int row16 = lane & 15;
    const int koff = (lane >> 4) * 4;
    const int q0 = blockIdx.x * 128;
    const int bh = blockIdx.y;
    const int b = bh >> 4, h = bh & 15;

    const uint32_t sQ = smem_u32(dsm);
    const uint32_t sK = smem_u32(dsm + AO_K);
    const uint32_t sV = smem_u32(dsm + AO_V);
    const uint32_t sPw = smem_u32(Ps) + (uint32_t)(w * 16 * PSTH) * 4;
    unsigned* Pw = Ps + w * 16 * PSTH;

    const int srow = tid >> 3;        // 0..31
    const int sseg = tid & 7;         // 0..7
    const __half* KbBase = Kh + (size_t)b * Ss * Dd + h * 64 + sseg * 8;
    const __half* VbBase = Vh + (size_t)b * Ss * Dd + h * 64 + sseg * 8;
    // pre-scaled half bias rows for this warp's two row groups
    const __half* bhBase = biasH + (size_t)b * Ss * Ss + (size_t)(q0 + w * 16 + g) * Ss;

#define A_ISSUE(st, it_) do {                                                  \
        _Pragma("unroll")                                                      \
        for (int _l = 0; _l < 2; _l++) {                                       \
            const int _row = srow + 32 * _l;                                   \
            const size_t _roff = (size_t)((it_) * KTILE + _row) * Dd;          \
            const uint32_t _off = (uint32_t)(_row * KSTH + sseg * 4) * 4;      \
            CP_ASYNC16(sK + (uint32_t)((st) * KBUFU) * 4 + _off, KbBase + _roff); \
            CP_ASYNC16(sV + (uint32_t)((st) * VBUFU) * 4 + _off, VbBase + _roff); \
        }                                                                      \
    } while (0)

    {
        A_ISSUE(0, 0);
        const __half* Qb = Q + ((size_t)b * Ss + q0) * Dd + h * 64 + sseg * 8;
#pragma unroll
        for (int l = 0; l < 4; l++) {
            const int row = srow + 32 * l;
            CP_ASYNC16(sQ + (uint32_t)(row * QSTH + sseg * 4) * 4,
                       Qb + (size_t)row * Dd);
        }
    }
    CP_COMMIT();
    A_ISSUE(1, 1);
    CP_COMMIT();

    // bias tile 0 prefetch: direct half2 loads (already scaled by log2e)
    unsigned pbh[8][2];
#pragma unroll
    for (int nt = 0; nt < 8; nt++)
#pragma unroll
        for (int rr = 0; rr < 2; rr++)
            pbh[nt][rr] = *(const unsigned*)(bhBase + (size_t)(rr * 8) * Ss + nt * 8 + 2 * t);

    CP_WAIT(1);
    __syncthreads();

    unsigned qa[4][4];
#pragma unroll
    for (int kk = 0; kk < 4; kk++) {
        const uint32_t addr = sQ +
            (uint32_t)((w * 16 + row16) * QSTH + kk * 8 + koff) * 4;
        LDSM_X4(qa[kk][0], qa[kk][1], qa[kk][2], qa[kk][3], addr);
    }

    float o[8][4] = {};
    float lr[2] = {};

    const int NIT = Ss / KTILE;   // 32
    for (int it = 0; it < NIT; it++) {
        if (it > 0) {
            CP_WAIT(1);
            __syncthreads();
        }
        if (it + 2 < NIT) A_ISSUE((it + 2) % 3, it + 2);
        CP_COMMIT();

        const uint32_t sKc = sK + (uint32_t)((it % 3) * KBUFU) * 4;
        const uint32_t vb = sV + (uint32_t)((it % 3) * VBUFU) * 4;

        float s[8][4] = {};
#pragma unroll
        for (int kk = 0; kk < 4; kk++) {
            const int kb = kk * 8;
#pragma unroll
            for (int ntp = 0; ntp < 4; ntp++) {
                unsigned kv[4];
                const uint32_t addr = sKc +
                    (uint32_t)((ntp * 16 + row16) * KSTH + kb + koff) * 4;
                LDSM_X4(kv[0], kv[1], kv[2], kv[3], addr);
                unsigned be[2] = {kv[0], kv[2]};
                unsigned bo2[2] = {kv[1], kv[3]};
                mma16(s[2 * ntp],     qa[kk], be);
                mma16(s[2 * ntp + 1], qa[kk], bo2);
            }
        }

#pragma unroll
        for (int nt = 0; nt < 8; nt++) {
            const float2 b0 = __half22float2(*(__half2*)&pbh[nt][0]);
            const float2 b1 = __half22float2(*(__half2*)&pbh[nt][1]);
            float p0 = exp2f(fmaf(s[nt][0], QPRE, b0.x));
            float p1 = exp2f(fmaf(s[nt][1], QPRE, b0.y));
            float p2 = exp2f(fmaf(s[nt][2], QPRE, b1.x));
            float p3 = exp2f(fmaf(s[nt][3], QPRE, b1.y));
            lr[0] += p0 + p1;
            lr[1] += p2 + p3;
            Pw[(g) * PSTH + nt * 4 + t]     = f2h2(p0, p1);
            Pw[(g + 8) * PSTH + nt * 4 + t] = f2h2(p2, p3);
        }

        if (it + 1 < NIT) {
            const __half* bp = bhBase + (it + 1) * KTILE;
#pragma unroll
            for (int nt = 0; nt < 8; nt++)
#pragma unroll
                for (int rr = 0; rr < 2; rr++)
                    pbh[nt][rr] = *(const unsigned*)(bp + (size_t)(rr * 8) * Ss + nt * 8 + 2 * t);
        }
        __syncwarp();

        const int m = lane >> 3, rr2 = lane & 7;
#pragma unroll
        for (int kk = 0; kk < 4; kk++) {
            const int kb = kk * 8;
            unsigned pa[4];
            const uint32_t paddr = sPw + (uint32_t)(row16 * PSTH + kb + koff) * 4;
            LDSM_X4(pa[0], pa[1], pa[2], pa[3], paddr);
#pragma unroll
            for (int ntp = 0; ntp < 4; ntp++) {
                const uint32_t vaddr = vb +
                    (uint32_t)((kk * 16 + (m & 1) * 8 + rr2) * VSTH +
                               (2 * ntp + (m >> 1)) * 4) * 4;
                unsigned bv[4];
                LDSM_X4_T(bv[0], bv[1], bv[2], bv[3], vaddr);
                mma16(o[2 * ntp],     pa, &bv[0]);
                mma16(o[2 * ntp + 1], pa, &bv[2]);
            }
        }
    }
#undef A_ISSUE

#pragma unroll
    for (int hf = 0; hf < 2; hf++) {
        float v = lr[hf];
        v += __shfl_xor_sync(0xffffffffu, v, 1);
        v += __shfl_xor_sync(0xffffffffu, v, 2);
        lr[hf] = 1.f / v;
    }

    __half* Ob = O + ((size_t)b * Ss + q0 + w * 16) * Dd + h * 64;
#pragma unroll
    for (int nt = 0; nt < 8; nt++) {
        const int cg = nt * 8 + 2 * t;
        *(unsigned*)(Ob + (size_t)g * Dd + cg) =
            f2h2(o[nt][0] * lr[0], o[nt][1] * lr[0]);
        *(unsigned*)(Ob + (size_t)(g + 8) * Dd + cg) =
            f2h2(o[nt][2] * lr[1], o[nt][3] * lr[1]);
    }
}

// ---------------------------------------------------------------------------
extern "C" void kernel_launch(void* const* d_in, const int* in_sizes, int n_in,
                              void* d_out, int out_size)
{
    (void)in_sizes; (void)n_in;
    const float* queries   = (const float*)d_in[0];
    const float* keys      = (const float*)d_in[1];
    const float* values    = (const float*)d_in[2];
    const float* attn_bias = (const float*)d_in[3];
    const float* Wq = (const float*)d_in[4];
    const float* bq = (const float*)d_in[5];
    const float* Wk = (const float*)d_in[6];
    const float* bk = (const float*)d_in[7];
    const float* Wv = (const float*)d_in[8];
    const float* bv = (const float*)d_in[9];
    const float* Wo = (const float*)d_in[10];
    const float* bo = (const float*)d_in[11];

    float* out = (float*)d_out;

    float *pkf, *pvf;
    cudaGetSymbolAddress((void**)&pkf, g_k);
    cudaGetSymbolAddress((void**)&pvf, g_v);
    __half *xq, *xk, *xv, *qh, *kh, *vh, *ah, *wqh, *wkh, *wvh, *woh, *bhp;
    cudaGetSymbolAddress((void**)&xq,  g_xq);
    cudaGetSymbolAddress((void**)&xk,  g_xk);
    cudaGetSymbolAddress((void**)&xv,  g_xv);
    cudaGetSymbolAddress((void**)&qh,  g_qh);
    cudaGetSymbolAddress((void**)&kh,  g_kh);
    cudaGetSymbolAddress((void**)&vh,  g_vh);
    cudaGetSymbolAddress((void**)&ah,  g_ah);
    cudaGetSymbolAddress((void**)&wqh, g_wqh);
    cudaGetSymbolAddress((void**)&wkh, g_wkh);
    cudaGetSymbolAddress((void**)&wvh, g_wvh);
    cudaGetSymbolAddress((void**)&woh, g_woh);
    cudaGetSymbolAddress((void**)&bhp, g_bh);

    const bool full_out = (out_size >= 3 * BSD);
    float* kdst = full_out ? out + BSD     : pkf;
    float* vdst = full_out ? out + 2 * BSD : pvf;

    cudaFuncSetAttribute(gemm_h, cudaFuncAttributeMaxDynamicSharedMemorySize,
                         GSM_BYTES);
    cudaFuncSetAttribute(qkv_gemm, cudaFuncAttributeMaxDynamicSharedMemorySize,
                         GSM_BYTES);
    cudaFuncSetAttribute(attn_h, cudaFuncAttributeMaxDynamicSharedMemorySize,
                         ATTN_SM_BYTES);

    // grid.x covers the largest slice (bias: 8.39M elems / 2048 per block)
    dim3 cgrid(BSS / (256 * 8), 8);              // (4096, 8)
    cvt8<<<cgrid, 256>>>(queries, keys, values, Wq, Wk, Wv, Wo, attn_bias,
                         xq, xk, xv, wqh, wkh, wvh, woh, bhp);

    dim3 qkvgrid(Dd / 128, (Bb * Ss) / 128, 3);  // (8, 32, 3)
    qkv_gemm<<<qkvgrid, 256, GSM_BYTES>>>(xq, xk, xv, wqh, wkh, wvh, bq, bk, bv,
                                          qh, kdst, kh, vdst, vh);

    dim3 agrid(Ss / 128, Bb * Hh);               // (16, 32)
    attn_h<<<agrid, 256, ATTN_SM_BYTES>>>(qh, kh, vh, bhp, ah);

    dim3 ggrid(Dd / 128, (Bb * Ss) / 128);       // (8, 32)
    gemm_h<<<ggrid, 256, GSM_BYTES>>>(ah, woh, bo, out, nullptr);
}

// round 17
// speedup vs baseline: 1.0276x; 1.0241x over previous
#include <cuda_runtime.h>
#include <cuda_fp16.h>
#include <cstdint>

#define Bb 2
#define Ss 2048
#define Dd 1024
#define Hh 16
#define BSD (Bb * Ss * Dd) /* 4194304 */
#define BSS (Bb * Ss * Ss) /* 8388608 */
#define DD (Dd * Dd)

// fp32 scratch (cache fallback)
static __device__ float g_k[BSD];
static __device__ float g_v[BSD];
// half scratch
static __device__ __half g_xq[BSD], g_xk[BSD], g_xv[BSD];
static __device__ __half g_qh[BSD], g_kh[BSD], g_vh[BSD];
static __device__ __half g_ah[BSD];
static __device__ __half g_wqh[DD], g_wkh[DD], g_wvh[DD], g_woh[DD];
static __device__ __half g_bh[BSS];   // bias * log2e, half

#define LOG2E 1.4426950408889634f
#define QPRE 0.18033688011112042f     /* 0.125 * log2(e) */

__device__ __forceinline__ unsigned f2h2(float lo, float hi) {
    __half2 h = __floats2half2_rn(lo, hi);
    return *(unsigned*)&h;
}

__device__ __forceinline__ void mma16(float* c, const unsigned* a, const unsigned* b) {
    asm volatile(
        "mma.sync.aligned.m16n8k16.row.col.f32.f16.f16.f32 "
        "{%0,%1,%2,%3}, {%4,%5,%6,%7}, {%8,%9}, {%0,%1,%2,%3};\n"
        : "+f"(c[0]), "+f"(c[1]), "+f"(c[2]), "+f"(c[3])
        : "r"(a[0]), "r"(a[1]), "r"(a[2]), "r"(a[3]), "r"(b[0]), "r"(b[1]));
}

__device__ __forceinline__ uint32_t smem_u32(const void* p) {
    uint32_t a;
    asm("{ .reg .u64 t; cvta.to.shared.u64 t, %1; cvt.u32.u64 %0, t; }"
        : "=r"(a) : "l"(p));
    return a;
}

#define CP_ASYNC16(dst, src) \
    asm volatile("cp.async.cg.shared.global [%0], [%1], 16;" :: "r"(dst), "l"(src))
#define CP_COMMIT() asm volatile("cp.async.commit_group;" ::: "memory")
#define CP_WAIT(n)  asm volatile("cp.async.wait_group %0;" :: "n"(n) : "memory")

#define LDSM_X4(r0, r1, r2, r3, addr)                                          \
    asm volatile("ldmatrix.sync.aligned.m8n8.x4.shared.b16 "                   \
                 "{%0,%1,%2,%3}, [%4];"                                        \
                 : "=r"(r0), "=r"(r1), "=r"(r2), "=r"(r3) : "r"(addr))

#define LDSM_X4_T(r0, r1, r2, r3, addr)                                        \
    asm volatile("ldmatrix.sync.aligned.m8n8.x4.trans.shared.b16 "             \
                 "{%0,%1,%2,%3}, [%4];"                                        \
                 : "=r"(r0), "=r"(r1), "=r"(r2), "=r"(r3) : "r"(addr))

// ===========================================================================
// Pre-convert fp32 -> fp16: 3 inputs, 4 weights, and bias*log2e. 8 elts/thr.
// ===========================================================================
__global__ __launch_bounds__(256, 4)
void cvt8(const float* q, const float* k, const float* v,
          const float* wq, const float* wk, const float* wv, const float* wo,
          const float* bias,
          __half* qh, __half* kh, __half* vh,
          __half* wqh, __half* wkh, __half* wvh, __half* woh, __half* bh)
{
    const int z = blockIdx.y;
    const float* s; __half* d; int n; float sc = 1.0f;
    switch (z) {
        case 0: s = q;  d = qh;  n = BSD; break;
        case 1: s = k;  d = kh;  n = BSD; break;
        case 2: s = v;  d = vh;  n = BSD; break;
        case 3: s = wq; d = wqh; n = DD;  break;
        case 4: s = wk; d = wkh; n = DD;  break;
        case 5: s = wv; d = wvh; n = DD;  break;
        case 6: s = wo; d = woh; n = DD;  break;
        default: s = bias; d = bh; n = BSS; sc = LOG2E; break;
    }
    const size_t i = ((size_t)blockIdx.x * 256 + threadIdx.x) * 8;
    if (i >= (size_t)n) return;
    const float4 a = *(const float4*)(s + i);
    const float4 b2 = *(const float4*)(s + i + 4);
    uint4 u = {f2h2(a.x * sc, a.y * sc), f2h2(a.z * sc, a.w * sc),
               f2h2(b2.x * sc, b2.y * sc), f2h2(b2.z * sc, b2.w * sc)};
    *(uint4*)(d + i) = u;
}

// ===========================================================================
// GEMM (half): C = A @ W^T + bias, N=K=1024 compile-time. 128x128 CTA tile,
// BK=64, 256 thr / 8 warps, warp tile 32x64, 3-stage cp.async pipeline,
// ONE syncthreads per chunk. 2 CTAs/SM. (R14 config — measured best.)
// ===========================================================================
#define GK 1024
#define GN 1024
#define GST64 36
#define GBUF64 (128 * GST64)
#define GSM_BYTES (6 * GBUF64 * 4)       /* 110592 */
#define GNCH 16

__device__ __forceinline__
void gemm_core(const __half* __restrict__ A, const __half* __restrict__ W,
               const float* __restrict__ bias, float* Cf, __half* Ch,
               int bm, int bn, unsigned* smbase)
{
    const int tid = threadIdx.x;
    const int w = tid >> 5, lane = tid & 31;
    const int g = lane >> 2, t = lane & 3;
    const int wm = (w & 3) * 32;
    const int wn = (w >> 2) * 64;
    const int row16 = lane & 15;
    const int koff = (lane >> 4) * 4;

    const uint32_t sA = smem_u32(smbase);
    const uint32_t sB = sA + (uint32_t)(3 * GBUF64) * 4;

    const int srow = tid >> 3;   // 0..31 (+32*l)
    const int sseg = tid & 7;    // 0..7

    float c[2][8][4] = {};

#define G_ISSUE(st, ch) do {                                                   \
        const int _k0 = (ch) * 64 + sseg * 8;                                  \
        _Pragma("unroll")                                                      \
        for (int _l = 0; _l < 4; _l++) {                                       \
            const int _row = srow + 32 * _l;                                   \
            const uint32_t _off =                                              \
                (uint32_t)((st) * GBUF64 + _row * GST64 + sseg * 4) * 4;       \
            CP_ASYNC16(sA + _off, A + (size_t)(bm + _row) * GK + _k0);         \
            CP_ASYNC16(sB + _off, W + (size_t)(bn + _row) * GK + _k0);         \
        }                                                                      \
    } while (0)

    G_ISSUE(0, 0); CP_COMMIT();
    G_ISSUE(1, 1); CP_COMMIT();

    for (int ch = 0; ch < GNCH; ch++) {
        CP_WAIT(1);
        __syncthreads();
        if (ch + 2 < GNCH) G_ISSUE((ch + 2) % 3, ch + 2);
        CP_COMMIT();

        const uint32_t sAc = sA + (uint32_t)((ch % 3) * GBUF64) * 4;
        const uint32_t sBc = sB + (uint32_t)((ch % 3) * GBUF64) * 4;
#pragma unroll
        for (int kk = 0; kk < 4; kk++) {
            const int kb = kk * 8;
            unsigned a[2][4];
#pragma unroll
            for (int mt = 0; mt < 2; mt++) {
                const uint32_t addr = sAc +
                    (uint32_t)((wm + mt * 16 + row16) * GST64 + kb + koff) * 4;
                LDSM_X4(a[mt][0], a[mt][1], a[mt][2], a[mt][3], addr);
            }
#pragma unroll
            for (int ntp = 0; ntp < 4; ntp++) {
                unsigned bv[4];
                const uint32_t addr = sBc +
                    (uint32_t)((wn + ntp * 16 + row16) * GST64 + kb + koff) * 4;
                LDSM_X4(bv[0], bv[1], bv[2], bv[3], addr);
                unsigned be[2] = {bv[0], bv[2]};
                unsigned bo2[2] = {bv[1], bv[3]};
                mma16(c[0][2 * ntp],     a[0], be);
                mma16(c[1][2 * ntp],     a[1], be);
                mma16(c[0][2 * ntp + 1], a[0], bo2);
                mma16(c[1][2 * ntp + 1], a[1], bo2);
            }
        }
    }
#undef G_ISSUE

#pragma unroll
    for (int mt = 0; mt < 2; mt++) {
        const int r0 = bm + wm + mt * 16 + g;
#pragma unroll
        for (int nt = 0; nt < 8; nt++) {
            const int col = bn + wn + nt * 8 + 2 * t;
            const float2 bv = *(const float2*)(bias + col);
            float2 o0 = {c[mt][nt][0] + bv.x, c[mt][nt][1] + bv.y};
            float2 o1 = {c[mt][nt][2] + bv.x, c[mt][nt][3] + bv.y};
            if (Cf) {
                *(float2*)(Cf + (size_t)r0 * GN + col) = o0;
                *(float2*)(Cf + (size_t)(r0 + 8) * GN + col) = o1;
            }
            if (Ch) {
                *(unsigned*)(Ch + (size_t)r0 * GN + col) = f2h2(o0.x, o0.y);
                *(unsigned*)(Ch + (size_t)(r0 + 8) * GN + col) = f2h2(o1.x, o1.y);
            }
        }
    }
}

__global__ __launch_bounds__(256, 2)
void gemm_h(const __half* __restrict__ A, const __half* __restrict__ W,
            const float* __restrict__ bias, float* Cf, __half* Ch)
{
    extern __shared__ unsigned dsm[];
    gemm_core(A, W, bias, Cf, Ch, blockIdx.y * 128, blockIdx.x * 128, dsm);
}

__global__ __launch_bounds__(256, 2)
void qkv_gemm(const __half* xq, const __half* xk, const __half* xv,
              const __half* wq, const __half* wk, const __half* wv,
              const float* b0, const float* b1, const float* b2,
              __half* qh, float* kf, __half* kh, float* vf, __half* vh)
{
    extern __shared__ unsigned dsm[];
    const int z = blockIdx.z;
    const __half* A = (z == 0) ? xq : (z == 1) ? xk : xv;
    const __half* W = (z == 0) ? wq : (z == 1) ? wk : wv;
    const float* bi = (z == 0) ? b0 : (z == 1) ? b1 : b2;
    float* Cf = (z == 0) ? nullptr : (z == 1) ? kf : vf;
    __half* Ch = (z == 0) ? qh : (z == 1) ? kh : vh;
    gemm_core(A, W, bi, Cf, Ch, blockIdx.y * 128, blockIdx.x * 128, dsm);
}

// ===========================================================================
// Attention: 256 thr / 8 warps (16 q-rows each), 2 CTAs/SM, k-tiles of 64
// (32 iterations). 3-stage cp.async K/V pipeline, ONE syncthreads/iter.
// Q fragments hoisted; bias loaded as pre-scaled half2 (g_bh).
// REGISTER-RESIDENT P: the m16n8k16 C-fragment layout equals the A-fragment
// layout, so exp'd S tiles are packed straight into PV A-fragments — no P
// smem buffer, no P stores/ldmatrix, no syncwarp.
// ===========================================================================
#define KTILE 64
#define QSTH 36
#define KSTH 36
#define VSTH 36
#define KBUFU (KTILE * KSTH)   /* 2304 */
#define VBUFU (KTILE * VSTH)   /* 2304 */
#define AO_K 4608
#define AO_V (AO_K + 3 * KBUFU)
#define ATTN_UINTS (AO_V + 3 * VBUFU)   /* 18432 */
#define ATTN_SM_BYTES (ATTN_UINTS * 4)  /* 73728 */

__global__ __launch_bounds__(256, 2)
void attn_h(const __half* __restrict__ Q, const __half* __restrict__ Kh,
            const __half* __restrict__ Vh, const __half* __restrict__ biasH,
            __half* __restrict__ O)
{
    extern __shared__ unsigned dsm[];

    const int tid = threadIdx.x;
    const int w = tid >> 5, lane = tid & 31;
    const int g = lane >> 2, t = lane & 3;
    const int row16 = lane & 15;
    const int koff = (lane >> 4) * 4;
    const int q0 = blockIdx.x * 128;
    const int bh = blockIdx.y;
    const int b = bh >> 4, h = bh & 15;

    const uint32_t sQ = smem_u32(dsm);
    const uint32_t sK = smem_u32(dsm + AO_K);
    const uint32_t sV = smem_u32(dsm + AO_V);

    const int srow = tid >> 3;        // 0..31
    const int sseg = tid & 7;         // 0..7
    const __half* KbBase = Kh + (size_t)b * Ss * Dd + h * 64 + sseg * 8;
    const __half* VbBase = Vh + (size_t)b * Ss * Dd + h * 64 + sseg * 8;
    const __half* bhBase = biasH + (size_t)b * Ss * Ss + (size_t)(q0 + w * 16 + g) * Ss;

#define A_ISSUE(st, it_) do {                                                  \
        _Pragma("unroll")                                                      \
        for (int _l = 0; _l < 2; _l++) {                                       \
            const int _row = srow + 32 * _l;                                   \
            const size_t _roff = (size_t)((it_) * KTILE + _row) * Dd;          \
            const uint32_t _off = (uint32_t)(_row * KSTH + sseg * 4) * 4;      \
            CP_ASYNC16(sK + (uint32_t)((st) * KBUFU) * 4 + _off, KbBase + _roff); \
            CP_ASYNC16(sV + (uint32_t)((st) * VBUFU) * 4 + _off, VbBase + _roff); \
        }                                                                      \
    } while (0)

    {
        A_ISSUE(0, 0);
        const __half* Qb = Q + ((size_t)b * Ss + q0) * Dd + h * 64 + sseg * 8;
#pragma unroll
        for (int l = 0; l < 4; l++) {
            const int row = srow + 32 * l;
            CP_ASYNC16(sQ + (uint32_t)(row * QSTH + sseg * 4) * 4,
                       Qb + (size_t)row * Dd);
        }
    }
    CP_COMMIT();
    A_ISSUE(1, 1);
    CP_COMMIT();

    // bias tile 0 prefetch: direct half2 loads (already scaled by log2e)
    unsigned pbh[8][2];
#pragma unroll
    for (int nt = 0; nt < 8; nt++)
#pragma unroll
        for (int rr = 0; rr < 2; rr++)
            pbh[nt][rr] = *(const unsigned*)(bhBase + (size_t)(rr * 8) * Ss + nt * 8 + 2 * t);

    CP_WAIT(1);
    __syncthreads();

    unsigned qa[4][4];
#pragma unroll
    for (int kk = 0; kk < 4; kk++) {
        const uint32_t addr = sQ +
            (uint32_t)((w * 16 + row16) * QSTH + kk * 8 + koff) * 4;
        LDSM_X4(qa[kk][0], qa[kk][1], qa[kk][2], qa[kk][3], addr);
    }

    float o[8][4] = {};
    float lr[2] = {};

    const int NIT = Ss / KTILE;   // 32
    for (int it = 0; it < NIT; it++) {
        if (it > 0) {
            CP_WAIT(1);
            __syncthreads();
        }
        if (it + 2 < NIT) A_ISSUE((it + 2) % 3, it + 2);
        CP_COMMIT();

        const uint32_t sKc = sK + (uint32_t)((it % 3) * KBUFU) * 4;
        const uint32_t vb = sV + (uint32_t)((it % 3) * VBUFU) * 4;

        // S = Q @ K^T : warp tile 16 x 64
        float s[8][4] = {};
#pragma unroll
        for (int kk = 0; kk < 4; kk++) {
            const int kb = kk * 8;
#pragma unroll
            for (int ntp = 0; ntp < 4; ntp++) {
                unsigned kv[4];
                const uint32_t addr = sKc +
                    (uint32_t)((ntp * 16 + row16) * KSTH + kb + koff) * 4;
                LDSM_X4(kv[0], kv[1], kv[2], kv[3], addr);
                unsigned be[2] = {kv[0], kv[2]};
                unsigned bo2[2] = {kv[1], kv[3]};
                mma16(s[2 * ntp],     qa[kk], be);
                mma16(s[2 * ntp + 1], qa[kk], bo2);
            }
        }

        // exp2(s*QPRE + bias') -> pack DIRECTLY into PV A-fragments pa[kk][4]
        //   pa[kk] covers keys [16kk, 16kk+16): a0/a1 from S-tile 2kk,
        //   a2/a3 from S-tile 2kk+1 (C-fragment == A-fragment layout).
        unsigned pa[4][4];
#pragma unroll
        for (int kk = 0; kk < 4; kk++) {
#pragma unroll
            for (int hf = 0; hf < 2; hf++) {
                const int nt = 2 * kk + hf;
                const float2 b0 = __half22float2(*(__half2*)&pbh[nt][0]);
                const float2 b1 = __half22float2(*(__half2*)&pbh[nt][1]);
                float p0 = exp2f(fmaf(s[nt][0], QPRE, b0.x));
                float p1 = exp2f(fmaf(s[nt][1], QPRE, b0.y));
                float p2 = exp2f(fmaf(s[nt][2], QPRE, b1.x));
                float p3 = exp2f(fmaf(s[nt][3], QPRE, b1.y));
                lr[0] += p0 + p1;
                lr[1] += p2 + p3;
                pa[kk][2 * hf + 0] = f2h2(p0, p1);   // rows g,   keys 2t..
                pa[kk][2 * hf + 1] = f2h2(p2, p3);   // rows g+8, keys 2t..
            }
        }

        // prefetch next bias tile
        if (it + 1 < NIT) {
            const __half* bp = bhBase + (it + 1) * KTILE;
#pragma unroll
            for (int nt = 0; nt < 8; nt++)
#pragma unroll
                for (int rr = 0; rr < 2; rr++)
                    pbh[nt][rr] = *(const unsigned*)(bp + (size_t)(rr * 8) * Ss + nt * 8 + 2 * t);
        }

        // O += P @ V : P fragments already in registers
        const int m = lane >> 3, rr2 = lane & 7;
#pragma unroll
        for (int kk = 0; kk < 4; kk++) {
#pragma unroll
            for (int ntp = 0; ntp < 4; ntp++) {
                const uint32_t vaddr = vb +
                    (uint32_t)((kk * 16 + (m & 1) * 8 + rr2) * VSTH +
                               (2 * ntp + (m >> 1)) * 4) * 4;
                unsigned bv[4];
                LDSM_X4_T(bv[0], bv[1], bv[2], bv[3], vaddr);
                mma16(o[2 * ntp],     pa[kk], &bv[0]);
                mma16(o[2 * ntp + 1], pa[kk], &bv[2]);
            }
        }
    }
#undef A_ISSUE

#pragma unroll
    for (int hf = 0; hf < 2; hf++) {
        float v = lr[hf];
        v += __shfl_xor_sync(0xffffffffu, v, 1);
        v += __shfl_xor_sync(0xffffffffu, v, 2);
        lr[hf] = 1.f / v;
    }

    __half* Ob = O + ((size_t)b * Ss + q0 + w * 16) * Dd + h * 64;
#pragma unroll
    for (int nt = 0; nt < 8; nt++) {
        const int cg = nt * 8 + 2 * t;
        *(unsigned*)(Ob + (size_t)g * Dd + cg) =
            f2h2(o[nt][0] * lr[0], o[nt][1] * lr[0]);
        *(unsigned*)(Ob + (size_t)(g + 8) * Dd + cg) =
            f2h2(o[nt][2] * lr[1], o[nt][3] * lr[1]);
    }
}

// ---------------------------------------------------------------------------
extern "C" void kernel_launch(void* const* d_in, const int* in_sizes, int n_in,
                              void* d_out, int out_size)
{
    (void)in_sizes; (void)n_in;
    const float* queries   = (const float*)d_in[0];
    const float* keys      = (const float*)d_in[1];
    const float* values    = (const float*)d_in[2];
    const float* attn_bias = (const float*)d_in[3];
    const float* Wq = (const float*)d_in[4];
    const float* bq = (const float*)d_in[5];
    const float* Wk = (const float*)d_in[6];
    const float* bk = (const float*)d_in[7];
    const float* Wv = (const float*)d_in[8];
    const float* bv = (const float*)d_in[9];
    const float* Wo = (const float*)d_in[10];
    const float* bo = (const float*)d_in[11];

    float* out = (float*)d_out;

    float *pkf, *pvf;
    cudaGetSymbolAddress((void**)&pkf, g_k);
    cudaGetSymbolAddress((void**)&pvf, g_v);
    __half *xq, *xk, *xv, *qh, *kh, *vh, *ah, *wqh, *wkh, *wvh, *woh, *bhp;
    cudaGetSymbolAddress((void**)&xq,  g_xq);
    cudaGetSymbolAddress((void**)&xk,  g_xk);
    cudaGetSymbolAddress((void**)&xv,  g_xv);
    cudaGetSymbolAddress((void**)&qh,  g_qh);
    cudaGetSymbolAddress((void**)&kh,  g_kh);
    cudaGetSymbolAddress((void**)&vh,  g_vh);
    cudaGetSymbolAddress((void**)&ah,  g_ah);
    cudaGetSymbolAddress((void**)&wqh, g_wqh);
    cudaGetSymbolAddress((void**)&wkh, g_wkh);
    cudaGetSymbolAddress((void**)&wvh, g_wvh);
    cudaGetSymbolAddress((void**)&woh, g_woh);
    cudaGetSymbolAddress((void**)&bhp, g_bh);

    const bool full_out = (out_size >= 3 * BSD);
    float* kdst = full_out ? out + BSD     : pkf;
    float* vdst = full_out ? out + 2 * BSD : pvf;

    cudaFuncSetAttribute(gemm_h, cudaFuncAttributeMaxDynamicSharedMemorySize,
                         GSM_BYTES);
    cudaFuncSetAttribute(qkv_gemm, cudaFuncAttributeMaxDynamicSharedMemorySize,
                         GSM_BYTES);
    cudaFuncSetAttribute(attn_h, cudaFuncAttributeMaxDynamicSharedMemorySize,
                         ATTN_SM_BYTES);

    dim3 cgrid(BSS / (256 * 8), 8);              // (4096, 8)
    cvt8<<<cgrid, 256>>>(queries, keys, values, Wq, Wk, Wv, Wo, attn_bias,
                         xq, xk, xv, wqh, wkh, wvh, woh, bhp);

    dim3 qkvgrid(Dd / 128, (Bb * Ss) / 128, 3);  // (8, 32, 3)
    qkv_gemm<<<qkvgrid, 256, GSM_BYTES>>>(xq, xk, xv, wqh, wkh, wvh, bq, bk, bv,
                                          qh, kdst, kh, vdst, vh);

    dim3 agrid(Ss / 128, Bb * Hh);               // (16, 32)
    attn_h<<<agrid, 256, ATTN_SM_BYTES>>>(qh, kh, vh, bhp, ah);

    dim3 ggrid(Dd / 128, (Bb * Ss) / 128);       // (8, 32)
    gemm_h<<<ggrid, 256, GSM_BYTES>>>(ah, woh, bo, out, nullptr);
}